// round 1
// baseline (speedup 1.0000x reference)
#include <cuda_runtime.h>
#include <math.h>

// ---------------------------------------------------------------------------
// LSTMEncDec: video 2-layer LSTM (B=64, 20 frames, C=8192) seeds a text
// 2-layer LSTM (B*NC=320 rows, 20 words, ragged mask), then linear decoder.
// Strategy: precompute all input-projection GEMMs (time-parallel), run the
// recurrence as fused (h@Whh + LSTM cell) kernels, 2 per timestep.
// ---------------------------------------------------------------------------

namespace cfg {
constexpr int B = 64, NC = 5, L = 20, F = 20, C = 8192, E = 300;
constexpr int H = 512, G4 = 2048, V = 8000;
constexpr int MT = B * NC;           // 320 text rows
constexpr int EP = 304;              // E padded to %8==0 for float4 GEMM loads
constexpr int BH = B * H;            // 32768
constexpr int MH = MT * H;           // 163840

constexpr size_t OFF_GV   = 0;                                    // [B*F, G4] row = b*20+t
constexpr size_t OFF_GT   = OFF_GV   + (size_t)B * F * G4;        // [MT*L, G4] row = m*20+t
constexpr size_t OFF_XT   = OFF_GT   + (size_t)MT * L * G4;       // [MT*L, EP]
constexpr size_t OFF_WT1P = OFF_XT   + (size_t)MT * L * EP;       // [G4, EP]
constexpr size_t OFF_VS0  = OFF_WT1P + (size_t)G4 * EP;           // vh1,vc1,vh2,vc2
constexpr size_t OFF_VS1  = OFF_VS0  + 4ull * BH;
constexpr size_t OFF_VRAW = OFF_VS1  + 4ull * BH;
constexpr size_t OFF_TS0  = OFF_VRAW + (size_t)BH;                // th1,tc1,th2,tc2
constexpr size_t OFF_TS1  = OFF_TS0  + 4ull * MH;
constexpr size_t OFF_TRAW = OFF_TS1  + 4ull * MH;
constexpr size_t OFF_ST   = OFF_TRAW + (size_t)MH;                // [MT, 2H]
constexpr size_t OFF_FE   = OFF_ST   + (size_t)MT * 2 * H;        // [MT, 2H]
constexpr size_t OFF_OUT  = OFF_FE   + (size_t)MT * 2 * H;        // [MT]
constexpr size_t TOTAL    = OFF_OUT  + (size_t)MT;
}  // namespace cfg

__device__ __align__(256) float g_scratch[cfg::TOTAL];

__device__ __forceinline__ float sigm(float x) { return 1.f / (1.f + expf(-x)); }

// ---------------------------------------------------------------------------
// Generic TN GEMM: C[M,N] = A[M,K] @ W[N,K]^T (+ bias[N]).
// 128x128x8 tile, 256 threads, 8x8 micro-tile (split 4+4 for conflict-free
// float4 smem reads). Requires K%8==0, rows 16B-aligned, N%128==0.
// ---------------------------------------------------------------------------
__global__ void __launch_bounds__(256) gemm_tn(
    const float* __restrict__ A, const float* __restrict__ W,
    const float* __restrict__ bias, float* __restrict__ Cmat,
    int M, int N, int K)
{
    __shared__ float sA[8][128];
    __shared__ float sB[8][128];
    const int tid = threadIdx.x;
    const int tx = tid & 15, ty = tid >> 4;
    const int bm = blockIdx.y * 128, bn = blockIdx.x * 128;
    const int lr = tid >> 1;
    const int lk = (tid & 1) << 2;
    const bool aok = (bm + lr) < M;
    const float* Arow = A + (size_t)(bm + lr) * K + lk;
    const float* Wrow = W + (size_t)(bn + lr) * K + lk;

    float acc[8][8] = {};

    for (int k0 = 0; k0 < K; k0 += 8) {
        float4 av = aok ? *(const float4*)(Arow + k0) : make_float4(0.f, 0.f, 0.f, 0.f);
        float4 wv = *(const float4*)(Wrow + k0);
        __syncthreads();
        sA[lk + 0][lr] = av.x; sA[lk + 1][lr] = av.y;
        sA[lk + 2][lr] = av.z; sA[lk + 3][lr] = av.w;
        sB[lk + 0][lr] = wv.x; sB[lk + 1][lr] = wv.y;
        sB[lk + 2][lr] = wv.z; sB[lk + 3][lr] = wv.w;
        __syncthreads();
#pragma unroll
        for (int kk = 0; kk < 8; kk++) {
            float4 a0 = *(const float4*)&sA[kk][ty * 4];
            float4 a1 = *(const float4*)&sA[kk][64 + ty * 4];
            float4 b0 = *(const float4*)&sB[kk][tx * 4];
            float4 b1 = *(const float4*)&sB[kk][64 + tx * 4];
            float af[8] = {a0.x, a0.y, a0.z, a0.w, a1.x, a1.y, a1.z, a1.w};
            float bf[8] = {b0.x, b0.y, b0.z, b0.w, b1.x, b1.y, b1.z, b1.w};
#pragma unroll
            for (int i = 0; i < 8; i++)
#pragma unroll
                for (int j = 0; j < 8; j++)
                    acc[i][j] += af[i] * bf[j];
        }
    }

#pragma unroll
    for (int i = 0; i < 8; i++) {
        int m = bm + (i < 4 ? ty * 4 + i : 64 + ty * 4 + (i - 4));
        if (m >= M) continue;
#pragma unroll
        for (int j = 0; j < 8; j++) {
            int n = bn + (j < 4 ? tx * 4 + j : 64 + tx * 4 + (j - 4));
            float v = acc[i][j];
            if (bias) v += bias[n];
            Cmat[(size_t)m * N + n] = v;
        }
    }
}

// ---------------------------------------------------------------------------
// Fused LSTM layer-1 step: gates = Gpre[t] (x@Wih+b precomputed) + h@Whh^T,
// then cell update. Block tile: TM=RPT*8 rows x 32 hidden units x all 4 gates.
// 128 threads: tx=tid%16 (2 cols), ty=tid/16 (RPT rows).
// Gpre row for batch m lives at (m*Tsteps + t)*2048.
// Writes: hraw (unmasked new h), hnext/cnext (masked).
// ---------------------------------------------------------------------------
template <int RPT>
__global__ void __launch_bounds__(128) lstm_l1(
    const float* __restrict__ Gpre, int t, int Tsteps,
    const float* __restrict__ Whh,
    const float* __restrict__ hcur, const float* __restrict__ ccur,
    float* __restrict__ hnext, float* __restrict__ cnext,
    float* __restrict__ hraw,
    const int* __restrict__ qlen, int M)
{
    constexpr int TM = RPT * 8;
    __shared__ float sH[16][TM];
    __shared__ float sW[4][16][32];
    const int tid = threadIdx.x;
    const int tx = tid & 15, ty = tid >> 4;
    const int m0 = blockIdx.y * TM;
    const int j0 = blockIdx.x * 32;

    float acc[4][RPT][2] = {};

    for (int k0 = 0; k0 < 512; k0 += 16) {
        // stage H tile: TM x 16 = TM*4 float4
        constexpr int HV = TM * 4;
        float4 hv = make_float4(0.f, 0.f, 0.f, 0.f);
        int hr = 0, hk = 0;
        if (tid < HV) {
            hr = tid >> 2; hk = (tid & 3) << 2;
            int m = m0 + hr;
            if (m < M) hv = *(const float4*)(hcur + (size_t)m * 512 + k0 + hk);
        }
        // stage W tile: 4 gates x 32 cols x 16 k = 512 float4, 4 per thread
        float4 wv[4]; int wg[4], wj[4], wk[4];
#pragma unroll
        for (int q = 0; q < 4; q++) {
            int v = tid + q * 128;
            wg[q] = v >> 7; int r = v & 127; wj[q] = r >> 2; wk[q] = (r & 3) << 2;
            wv[q] = *(const float4*)(Whh + (size_t)(wg[q] * 512 + j0 + wj[q]) * 512 + k0 + wk[q]);
        }
        __syncthreads();
        if (tid < HV) {
            sH[hk + 0][hr] = hv.x; sH[hk + 1][hr] = hv.y;
            sH[hk + 2][hr] = hv.z; sH[hk + 3][hr] = hv.w;
        }
#pragma unroll
        for (int q = 0; q < 4; q++) {
            sW[wg[q]][wk[q] + 0][wj[q]] = wv[q].x;
            sW[wg[q]][wk[q] + 1][wj[q]] = wv[q].y;
            sW[wg[q]][wk[q] + 2][wj[q]] = wv[q].z;
            sW[wg[q]][wk[q] + 3][wj[q]] = wv[q].w;
        }
        __syncthreads();
#pragma unroll
        for (int kk = 0; kk < 16; kk++) {
            float hf[RPT];
#pragma unroll
            for (int i = 0; i < RPT; i++) hf[i] = sH[kk][ty * RPT + i];
            float2 wf[4];
#pragma unroll
            for (int g = 0; g < 4; g++) wf[g] = *(const float2*)&sW[g][kk][tx * 2];
#pragma unroll
            for (int g = 0; g < 4; g++)
#pragma unroll
                for (int i = 0; i < RPT; i++) {
                    acc[g][i][0] += hf[i] * wf[g].x;
                    acc[g][i][1] += hf[i] * wf[g].y;
                }
        }
    }

#pragma unroll
    for (int i = 0; i < RPT; i++) {
        int m = m0 + ty * RPT + i;
        if (m >= M) continue;
        bool act = true;
        if (qlen) act = t < qlen[m / cfg::NC];
        const float* gp = Gpre + ((size_t)m * Tsteps + t) * 2048;
#pragma unroll
        for (int jj = 0; jj < 2; jj++) {
            int j = j0 + tx * 2 + jj;
            float gi = acc[0][i][jj] + gp[j];
            float gf = acc[1][i][jj] + gp[512 + j];
            float gg = acc[2][i][jj] + gp[1024 + j];
            float go = acc[3][i][jj] + gp[1536 + j];
            float co = ccur[(size_t)m * 512 + j];
            float cn = sigm(gf) * co + sigm(gi) * tanhf(gg);
            float hn = sigm(go) * tanhf(cn);
            hraw[(size_t)m * 512 + j] = hn;
            if (!act) { hn = hcur[(size_t)m * 512 + j]; cn = co; }
            hnext[(size_t)m * 512 + j] = hn;
            cnext[(size_t)m * 512 + j] = cn;
        }
    }
}

// ---------------------------------------------------------------------------
// Fused LSTM layer-2 step: gates = b + x@Wih^T + h@Whh^T, cell, mask.
// x = unmasked new h1 of this step (matches reference semantics).
// ---------------------------------------------------------------------------
template <int RPT>
__global__ void __launch_bounds__(128) lstm_l2(
    const float* __restrict__ x,    const float* __restrict__ Wih,
    const float* __restrict__ hcur, const float* __restrict__ Whh,
    const float* __restrict__ bias,
    const float* __restrict__ ccur,
    float* __restrict__ hnext, float* __restrict__ cnext,
    const int* __restrict__ qlen, int t, int M)
{
    constexpr int TM = RPT * 8;
    __shared__ float sH[16][TM];
    __shared__ float sW[4][16][32];
    const int tid = threadIdx.x;
    const int tx = tid & 15, ty = tid >> 4;
    const int m0 = blockIdx.y * TM;
    const int j0 = blockIdx.x * 32;

    float acc[4][RPT][2] = {};

    for (int s = 0; s < 2; s++) {
        const float* src = s ? hcur : x;
        const float* Wm  = s ? Whh  : Wih;
        for (int k0 = 0; k0 < 512; k0 += 16) {
            constexpr int HV = TM * 4;
            float4 hv = make_float4(0.f, 0.f, 0.f, 0.f);
            int hr = 0, hk = 0;
            if (tid < HV) {
                hr = tid >> 2; hk = (tid & 3) << 2;
                int m = m0 + hr;
                if (m < M) hv = *(const float4*)(src + (size_t)m * 512 + k0 + hk);
            }
            float4 wv[4]; int wg[4], wj[4], wk[4];
#pragma unroll
            for (int q = 0; q < 4; q++) {
                int v = tid + q * 128;
                wg[q] = v >> 7; int r = v & 127; wj[q] = r >> 2; wk[q] = (r & 3) << 2;
                wv[q] = *(const float4*)(Wm + (size_t)(wg[q] * 512 + j0 + wj[q]) * 512 + k0 + wk[q]);
            }
            __syncthreads();
            if (tid < HV) {
                sH[hk + 0][hr] = hv.x; sH[hk + 1][hr] = hv.y;
                sH[hk + 2][hr] = hv.z; sH[hk + 3][hr] = hv.w;
            }
#pragma unroll
            for (int q = 0; q < 4; q++) {
                sW[wg[q]][wk[q] + 0][wj[q]] = wv[q].x;
                sW[wg[q]][wk[q] + 1][wj[q]] = wv[q].y;
                sW[wg[q]][wk[q] + 2][wj[q]] = wv[q].z;
                sW[wg[q]][wk[q] + 3][wj[q]] = wv[q].w;
            }
            __syncthreads();
#pragma unroll
            for (int kk = 0; kk < 16; kk++) {
                float hf[RPT];
#pragma unroll
                for (int i = 0; i < RPT; i++) hf[i] = sH[kk][ty * RPT + i];
                float2 wf[4];
#pragma unroll
                for (int g = 0; g < 4; g++) wf[g] = *(const float2*)&sW[g][kk][tx * 2];
#pragma unroll
                for (int g = 0; g < 4; g++)
#pragma unroll
                    for (int i = 0; i < RPT; i++) {
                        acc[g][i][0] += hf[i] * wf[g].x;
                        acc[g][i][1] += hf[i] * wf[g].y;
                    }
            }
        }
    }

#pragma unroll
    for (int i = 0; i < RPT; i++) {
        int m = m0 + ty * RPT + i;
        if (m >= M) continue;
        bool act = true;
        if (qlen) act = t < qlen[m / cfg::NC];
#pragma unroll
        for (int jj = 0; jj < 2; jj++) {
            int j = j0 + tx * 2 + jj;
            float gi = acc[0][i][jj] + bias[j];
            float gf = acc[1][i][jj] + bias[512 + j];
            float gg = acc[2][i][jj] + bias[1024 + j];
            float go = acc[3][i][jj] + bias[1536 + j];
            float co = ccur[(size_t)m * 512 + j];
            float cn = sigm(gf) * co + sigm(gi) * tanhf(gg);
            float hn = sigm(go) * tanhf(cn);
            if (!act) { hn = hcur[(size_t)m * 512 + j]; cn = co; }
            hnext[(size_t)m * 512 + j] = hn;
            cnext[(size_t)m * 512 + j] = cn;
        }
    }
}

// ---------------------------------------------------------------------------
// Small helper kernels
// ---------------------------------------------------------------------------
__global__ void pad_w_k(const float* __restrict__ src, float* __restrict__ dst) {
    int i = blockIdx.x * 256 + threadIdx.x;
    if (i >= cfg::G4 * cfg::EP) return;
    int n = i / cfg::EP, k = i - n * cfg::EP;
    dst[i] = (k < cfg::E) ? src[(size_t)n * cfg::E + k] : 0.f;
}

__global__ void embed_gather_k(const int* __restrict__ q, const float* __restrict__ emb,
                               float* __restrict__ dst) {
    int i = blockIdx.x * 256 + threadIdx.x;
    if (i >= cfg::MT * cfg::L * cfg::EP) return;
    int r = i / cfg::EP, k = i - r * cfg::EP;   // r = m*20 + t, matches questions flat
    dst[i] = (k < cfg::E) ? emb[(size_t)q[r] * cfg::E + k] : 0.f;
}

__global__ void zero_k(float* __restrict__ p, int n) {
    int i = blockIdx.x * 256 + threadIdx.x;
    if (i < n) p[i] = 0.f;
}

__global__ void bcast_states_k(const float* __restrict__ vs, float* __restrict__ ts) {
    int i = blockIdx.x * 256 + threadIdx.x;
    if (i >= 4 * cfg::MH) return;
    int a = i / cfg::MH;
    int r = i - a * cfg::MH;
    int m = r / cfg::H, j = r - m * cfg::H;
    ts[i] = vs[(size_t)a * cfg::BH + (size_t)(m / cfg::NC) * cfg::H + j];
}

__global__ void concat_k(const float* __restrict__ h1, const float* __restrict__ h2,
                         float* __restrict__ st) {
    int i = blockIdx.x * 256 + threadIdx.x;
    if (i >= cfg::MT * 2 * cfg::H) return;
    int m = i / (2 * cfg::H), j = i - m * 2 * cfg::H;
    st[i] = (j < cfg::H) ? h1[(size_t)m * cfg::H + j]
                         : h2[(size_t)m * cfg::H + (j - cfg::H)];
}

__global__ void rowdot_k(const float* __restrict__ fe, const float* __restrict__ w,
                         const float* __restrict__ b, float* __restrict__ out) {
    int warp = (blockIdx.x * blockDim.x + threadIdx.x) >> 5;
    int lane = threadIdx.x & 31;
    if (warp >= cfg::MT) return;
    const float* row = fe + (size_t)warp * (2 * cfg::H);
    float s = 0.f;
    for (int k = lane; k < 2 * cfg::H; k += 32) s += row[k] * w[k];
#pragma unroll
    for (int o = 16; o; o >>= 1) s += __shfl_xor_sync(0xffffffffu, s, o);
    if (lane == 0) out[warp] = s + b[0];
}

// d_out layout guess: outputs[320] (row-major [B,NC]) then predictions[64] as
// float (argmax over NC, first-max wins). Zero-fill any extra tail.
__global__ void finalize_k(const float* __restrict__ outv, float* __restrict__ dout,
                           int out_size) {
    int i = blockIdx.x * 256 + threadIdx.x;
    if (i >= out_size) return;
    if (i < cfg::MT) {
        dout[i] = outv[i];
    } else if (i < cfg::MT + cfg::B) {
        int b = i - cfg::MT;
        float best = outv[b * cfg::NC]; int bi = 0;
#pragma unroll
        for (int nc = 1; nc < cfg::NC; nc++) {
            float v = outv[b * cfg::NC + nc];
            if (v > best) { best = v; bi = nc; }
        }
        dout[i] = (float)bi;
    } else {
        dout[i] = 0.f;
    }
}

// ---------------------------------------------------------------------------
// Host launcher (graph-capturable: kernel launches only)
// ---------------------------------------------------------------------------
extern "C" void kernel_launch(void* const* d_in, const int* in_sizes, int n_in,
                              void* d_out, int out_size) {
    using namespace cfg;
    const float* vf       = (const float*)d_in[0];
    const int*   questions= (const int*)  d_in[1];
    const int*   qlen     = (const int*)  d_in[2];
    const float* embw     = (const float*)d_in[3];
    const float* Wih_t1   = (const float*)d_in[4];
    const float* Whh_t1   = (const float*)d_in[5];
    const float* b_t1     = (const float*)d_in[6];
    const float* Wih_t2   = (const float*)d_in[7];
    const float* Whh_t2   = (const float*)d_in[8];
    const float* b_t2     = (const float*)d_in[9];
    const float* Wih_v1   = (const float*)d_in[10];
    const float* Whh_v1   = (const float*)d_in[11];
    const float* b_v1     = (const float*)d_in[12];
    const float* Wih_v2   = (const float*)d_in[13];
    const float* Whh_v2   = (const float*)d_in[14];
    const float* b_v2     = (const float*)d_in[15];
    const float* dec1_w   = (const float*)d_in[16];
    const float* dec1_b   = (const float*)d_in[17];
    const float* dec2_w   = (const float*)d_in[18];
    const float* dec2_b   = (const float*)d_in[19];
    (void)in_sizes; (void)n_in;

    float* S = nullptr;
    cudaGetSymbolAddress((void**)&S, g_scratch);
    float* GV   = S + OFF_GV;
    float* GT   = S + OFF_GT;
    float* XT   = S + OFF_XT;
    float* WT1P = S + OFF_WT1P;
    float* VS0  = S + OFF_VS0;
    float* VS1  = S + OFF_VS1;
    float* VRAW = S + OFF_VRAW;
    float* TS0  = S + OFF_TS0;
    float* TS1  = S + OFF_TS1;
    float* TRAW = S + OFF_TRAW;
    float* ST   = S + OFF_ST;
    float* FE   = S + OFF_FE;
    float* OUTV = S + OFF_OUT;
    float* dout = (float*)d_out;

    // Stage padded weight + gathered/padded embeddings
    pad_w_k<<<(G4 * EP + 255) / 256, 256>>>(Wih_t1, WT1P);
    embed_gather_k<<<(MT * L * EP + 255) / 256, 256>>>(questions, embw, XT);

    // Big time-parallel input-gate GEMMs
    gemm_tn<<<dim3(G4 / 128, (B * F) / 128), 256>>>(vf, Wih_v1, b_v1, GV, B * F, G4, C);
    gemm_tn<<<dim3(G4 / 128, (MT * L) / 128), 256>>>(XT, WT1P, b_t1, GT, MT * L, G4, EP);

    // Video recurrence (zero init states)
    zero_k<<<(4 * BH + 255) / 256, 256>>>(VS0, 4 * BH);
    for (int t = 0; t < F; t++) {
        float* cur = (t & 1) ? VS1 : VS0;
        float* nxt = (t & 1) ? VS0 : VS1;
        lstm_l1<2><<<dim3(16, B / 16), 128>>>(GV, t, F, Whh_v1,
                                              cur, cur + BH, nxt, nxt + BH,
                                              VRAW, nullptr, B);
        lstm_l2<2><<<dim3(16, B / 16), 128>>>(VRAW, Wih_v2,
                                              cur + 2 * BH, Whh_v2, b_v2,
                                              cur + 3 * BH, nxt + 2 * BH, nxt + 3 * BH,
                                              nullptr, t, B);
    }

    // Seed text states from final (even step count -> finals live in VS0)
    bcast_states_k<<<(4 * MH + 255) / 256, 256>>>(VS0, TS0);

    // Text recurrence with ragged mask
    for (int t = 0; t < L; t++) {
        float* cur = (t & 1) ? TS1 : TS0;
        float* nxt = (t & 1) ? TS0 : TS1;
        lstm_l1<4><<<dim3(16, MT / 32), 128>>>(GT, t, L, Whh_t1,
                                               cur, cur + MH, nxt, nxt + MH,
                                               TRAW, qlen, MT);
        lstm_l2<4><<<dim3(16, MT / 32), 128>>>(TRAW, Wih_t2,
                                               cur + 2 * MH, Whh_t2, b_t2,
                                               cur + 3 * MH, nxt + 2 * MH, nxt + 3 * MH,
                                               qlen, t, MT);
    }

    // Decoder
    concat_k<<<(MT * 2 * H + 255) / 256, 256>>>(TS0, TS0 + 2 * MH, ST);
    gemm_tn<<<dim3((2 * H) / 128, (MT + 127) / 128), 256>>>(ST, dec1_w, dec1_b, FE,
                                                            MT, 2 * H, 2 * H);
    rowdot_k<<<40, 256>>>(FE, dec2_w, dec2_b, OUTV);
    finalize_k<<<(out_size + 255) / 256, 256>>>(OUTV, dout, out_size);
}

// round 2
// speedup vs baseline: 1.4806x; 1.4806x over previous
#include <cuda_runtime.h>
#include <math.h>

// ---------------------------------------------------------------------------
// LSTMEncDec: video 2-layer LSTM (B=64, 20 frames, C=8192) seeds a text
// 2-layer LSTM (B*NC=320 rows, 20 words, ragged mask), then linear decoder.
// R2: double-buffered GEMM (BK=16) + rebuilt step kernels (256 thr, BK=32,
// single-sync double-buffered smem, conflict-free padded layouts).
// ---------------------------------------------------------------------------

namespace cfg {
constexpr int B = 64, NC = 5, L = 20, F = 20, C = 8192, E = 300;
constexpr int H = 512, G4 = 2048, V = 8000;
constexpr int MT = B * NC;           // 320 text rows
constexpr int EP = 304;              // E padded to %16==0 for GEMM chunking
constexpr int BH = B * H;            // 32768
constexpr int MH = MT * H;           // 163840

constexpr size_t OFF_GV   = 0;                                    // [B*F, G4] row = b*20+t
constexpr size_t OFF_GT   = OFF_GV   + (size_t)B * F * G4;        // [MT*L, G4] row = m*20+t
constexpr size_t OFF_XT   = OFF_GT   + (size_t)MT * L * G4;       // [MT*L, EP]
constexpr size_t OFF_WT1P = OFF_XT   + (size_t)MT * L * EP;       // [G4, EP]
constexpr size_t OFF_VS0  = OFF_WT1P + (size_t)G4 * EP;           // vh1,vc1,vh2,vc2
constexpr size_t OFF_VS1  = OFF_VS0  + 4ull * BH;
constexpr size_t OFF_VRAW = OFF_VS1  + 4ull * BH;
constexpr size_t OFF_TS0  = OFF_VRAW + (size_t)BH;                // th1,tc1,th2,tc2
constexpr size_t OFF_TS1  = OFF_TS0  + 4ull * MH;
constexpr size_t OFF_TRAW = OFF_TS1  + 4ull * MH;
constexpr size_t OFF_ST   = OFF_TRAW + (size_t)MH;                // [MT, 2H]
constexpr size_t OFF_FE   = OFF_ST   + (size_t)MT * 2 * H;        // [MT, 2H]
constexpr size_t OFF_OUT  = OFF_FE   + (size_t)MT * 2 * H;        // [MT]
constexpr size_t TOTAL    = OFF_OUT  + (size_t)MT;
}  // namespace cfg

__device__ __align__(256) float g_scratch[cfg::TOTAL];

__device__ __forceinline__ float sigm(float x) { return 1.f / (1.f + expf(-x)); }

// ---------------------------------------------------------------------------
// TN GEMM: C[M,N] = A[M,K] @ W[N,K]^T (+ bias[N]).
// 128x128x16 tile, 256 threads, 8x8 micro-tile, double-buffered smem with a
// single __syncthreads per K-chunk (prefetch-to-regs overlaps compute).
// Requires K%16==0, rows 16B-aligned, N%128==0.
// ---------------------------------------------------------------------------
__global__ void __launch_bounds__(256) gemm_tn(
    const float* __restrict__ A, const float* __restrict__ W,
    const float* __restrict__ bias, float* __restrict__ Cmat,
    int M, int N, int K)
{
    __shared__ float sA[2][16][128];
    __shared__ float sB[2][16][128];
    const int tid = threadIdx.x;
    const int tx = tid & 15, ty = tid >> 4;
    const int bm = blockIdx.y * 128, bn = blockIdx.x * 128;
    const int lr = tid >> 1;
    const int lk = (tid & 1) << 2;
    const bool aok = (bm + lr) < M;
    const float* Arow = A + (size_t)(bm + lr) * K + lk;
    const float* Wrow = W + (size_t)(bn + lr) * K + lk;
    const float4 z4 = make_float4(0.f, 0.f, 0.f, 0.f);

    float acc[8][8] = {};
    float4 a0, a1, w0, w1;

    a0 = aok ? *(const float4*)(Arow)     : z4;
    a1 = aok ? *(const float4*)(Arow + 8) : z4;
    w0 = *(const float4*)(Wrow);
    w1 = *(const float4*)(Wrow + 8);

    sA[0][lk + 0][lr] = a0.x; sA[0][lk + 1][lr] = a0.y;
    sA[0][lk + 2][lr] = a0.z; sA[0][lk + 3][lr] = a0.w;
    sA[0][lk + 8][lr] = a1.x; sA[0][lk + 9][lr] = a1.y;
    sA[0][lk +10][lr] = a1.z; sA[0][lk +11][lr] = a1.w;
    sB[0][lk + 0][lr] = w0.x; sB[0][lk + 1][lr] = w0.y;
    sB[0][lk + 2][lr] = w0.z; sB[0][lk + 3][lr] = w0.w;
    sB[0][lk + 8][lr] = w1.x; sB[0][lk + 9][lr] = w1.y;
    sB[0][lk +10][lr] = w1.z; sB[0][lk +11][lr] = w1.w;
    __syncthreads();

    int buf = 0;
    for (int k0 = 0; k0 < K; k0 += 16) {
        const bool more = (k0 + 16) < K;
        if (more) {
            a0 = aok ? *(const float4*)(Arow + k0 + 16) : z4;
            a1 = aok ? *(const float4*)(Arow + k0 + 24) : z4;
            w0 = *(const float4*)(Wrow + k0 + 16);
            w1 = *(const float4*)(Wrow + k0 + 24);
        }
#pragma unroll
        for (int kk = 0; kk < 16; kk++) {
            float4 x0 = *(const float4*)&sA[buf][kk][ty * 4];
            float4 x1 = *(const float4*)&sA[buf][kk][64 + ty * 4];
            float4 y0 = *(const float4*)&sB[buf][kk][tx * 4];
            float4 y1 = *(const float4*)&sB[buf][kk][64 + tx * 4];
            float af[8] = {x0.x, x0.y, x0.z, x0.w, x1.x, x1.y, x1.z, x1.w};
            float bf[8] = {y0.x, y0.y, y0.z, y0.w, y1.x, y1.y, y1.z, y1.w};
#pragma unroll
            for (int i = 0; i < 8; i++)
#pragma unroll
                for (int j = 0; j < 8; j++)
                    acc[i][j] += af[i] * bf[j];
        }
        if (more) {
            int b2 = buf ^ 1;
            sA[b2][lk + 0][lr] = a0.x; sA[b2][lk + 1][lr] = a0.y;
            sA[b2][lk + 2][lr] = a0.z; sA[b2][lk + 3][lr] = a0.w;
            sA[b2][lk + 8][lr] = a1.x; sA[b2][lk + 9][lr] = a1.y;
            sA[b2][lk +10][lr] = a1.z; sA[b2][lk +11][lr] = a1.w;
            sB[b2][lk + 0][lr] = w0.x; sB[b2][lk + 1][lr] = w0.y;
            sB[b2][lk + 2][lr] = w0.z; sB[b2][lk + 3][lr] = w0.w;
            sB[b2][lk + 8][lr] = w1.x; sB[b2][lk + 9][lr] = w1.y;
            sB[b2][lk +10][lr] = w1.z; sB[b2][lk +11][lr] = w1.w;
            __syncthreads();
            buf ^= 1;
        }
    }

#pragma unroll
    for (int i = 0; i < 8; i++) {
        int m = bm + (i < 4 ? ty * 4 + i : 64 + ty * 4 + (i - 4));
        if (m >= M) continue;
#pragma unroll
        for (int j = 0; j < 8; j++) {
            int n = bn + (j < 4 ? tx * 4 + j : 64 + tx * 4 + (j - 4));
            float v = acc[i][j];
            if (bias) v += bias[n];
            Cmat[(size_t)m * N + n] = v;
        }
    }
}

// ---------------------------------------------------------------------------
// Fused LSTM step kernel (both layers via template):
//   L2=false: gates = Gpre[(m*Tsteps+t)*2048 + col] + src0 @ W0^T
//             (src0 = h_cur, W0 = Whh). Writes hraw (unmasked) + masked h,c.
//   L2=true:  gates = bias[col] + src0 @ W0^T + src1 @ W1^T
//             (src0 = new h1 raw, W0 = Wih2, src1 = h2_cur, W1 = Whh2).
// Block: 256 threads (tx=tid%16 -> hidden col j, ty=tid/16 -> RPT rows),
// tile = (16*RPT rows) x (16 j) x (4 gates). BK=32, double-buffered smem,
// one __syncthreads per chunk. Padded [row][33] layouts: conflict-free.
// Requires M % (16*RPT) == 0.
// ---------------------------------------------------------------------------
template <int RPT, bool L2>
__global__ void __launch_bounds__(256) lstm_step(
    const float* __restrict__ src0, const float* __restrict__ W0,
    const float* __restrict__ src1, const float* __restrict__ W1,
    const float* __restrict__ Gpre, const float* __restrict__ bias,
    int t, int Tsteps,
    const float* __restrict__ hprev, const float* __restrict__ cprev,
    float* __restrict__ hnext, float* __restrict__ cnext,
    float* __restrict__ hraw,
    const int* __restrict__ qlen, int M)
{
    constexpr int BM = 16 * RPT;
    constexpr int BK = 32;
    constexpr int NCH = L2 ? 32 : 16;            // K chunks (512 or 1024 total)
    constexpr int HV4 = BM * BK / 4;             // float4s in H tile
    constexpr int NHQ = (HV4 + 255) / 256;
    __shared__ float sH[2][BM][BK + 1];
    __shared__ float sW[2][64][BK + 1];

    const int tid = threadIdx.x;
    const int tx = tid & 15, ty = tid >> 4;
    const int j0 = blockIdx.x * 16;
    const int m0 = blockIdx.y * BM;

    float acc[4][RPT];
#pragma unroll
    for (int g = 0; g < 4; g++)
#pragma unroll
        for (int r = 0; r < RPT; r++) acc[g][r] = 0.f;

    float4 hv[NHQ];
    float4 wv[2];

    // Load one K-chunk into registers (H tile rows + 64 gate-col W rows)
    auto load_chunk = [&](int c) {
        const float* s = src0;
        const float* Wm = W0;
        int kpos = c * BK;
        if (L2 && c >= 16) { s = src1; Wm = W1; kpos = (c - 16) * BK; }
#pragma unroll
        for (int q = 0; q < NHQ; q++) {
            int v = tid + q * 256;
            if (HV4 < 256 * (q + 1) && v >= HV4) continue;
            int p = v >> 3, k4 = (v & 7) << 2;
            hv[q] = *(const float4*)(s + (size_t)(m0 + p) * 512 + kpos + k4);
        }
#pragma unroll
        for (int q = 0; q < 2; q++) {
            int v = tid + q * 256;
            int p = v >> 3, k4 = (v & 7) << 2;
            int gc = ((p >> 4) * 512) + j0 + (p & 15);  // gate row in [0,2048)
            wv[q] = *(const float4*)(Wm + (size_t)gc * 512 + kpos + k4);
        }
    };
    auto store_chunk = [&](int b) {
#pragma unroll
        for (int q = 0; q < NHQ; q++) {
            int v = tid + q * 256;
            if (HV4 < 256 * (q + 1) && v >= HV4) continue;
            int p = v >> 3, k4 = (v & 7) << 2;
            sH[b][p][k4 + 0] = hv[q].x; sH[b][p][k4 + 1] = hv[q].y;
            sH[b][p][k4 + 2] = hv[q].z; sH[b][p][k4 + 3] = hv[q].w;
        }
#pragma unroll
        for (int q = 0; q < 2; q++) {
            int v = tid + q * 256;
            int p = v >> 3, k4 = (v & 7) << 2;
            sW[b][p][k4 + 0] = wv[q].x; sW[b][p][k4 + 1] = wv[q].y;
            sW[b][p][k4 + 2] = wv[q].z; sW[b][p][k4 + 3] = wv[q].w;
        }
    };

    load_chunk(0);
    store_chunk(0);
    __syncthreads();
    int buf = 0;

    for (int c = 0; c < NCH; c++) {
        if (c + 1 < NCH) load_chunk(c + 1);
#pragma unroll
        for (int kk = 0; kk < BK; kk++) {
            float g0 = sW[buf][tx][kk];
            float g1 = sW[buf][16 + tx][kk];
            float g2 = sW[buf][32 + tx][kk];
            float g3 = sW[buf][48 + tx][kk];
            float h[RPT];
#pragma unroll
            for (int r = 0; r < RPT; r++) h[r] = sH[buf][ty * RPT + r][kk];
#pragma unroll
            for (int r = 0; r < RPT; r++) {
                acc[0][r] += h[r] * g0;
                acc[1][r] += h[r] * g1;
                acc[2][r] += h[r] * g2;
                acc[3][r] += h[r] * g3;
            }
        }
        if (c + 1 < NCH) {
            store_chunk(buf ^ 1);
            __syncthreads();
            buf ^= 1;
        }
    }

    const int j = j0 + tx;
    float bgi = 0.f, bgf = 0.f, bgg = 0.f, bgo = 0.f;
    if (L2) {
        bgi = bias[j]; bgf = bias[512 + j]; bgg = bias[1024 + j]; bgo = bias[1536 + j];
    }
#pragma unroll
    for (int r = 0; r < RPT; r++) {
        int m = m0 + ty * RPT + r;
        if (!L2) {
            const float* gp = Gpre + ((size_t)m * Tsteps + t) * 2048;
            bgi = gp[j]; bgf = gp[512 + j]; bgg = gp[1024 + j]; bgo = gp[1536 + j];
        }
        float gi = acc[0][r] + bgi;
        float gf = acc[1][r] + bgf;
        float gg = acc[2][r] + bgg;
        float go = acc[3][r] + bgo;
        size_t off = (size_t)m * 512 + j;
        float co = cprev[off];
        float cn = sigm(gf) * co + sigm(gi) * tanhf(gg);
        float hn = sigm(go) * tanhf(cn);
        if (!L2) hraw[off] = hn;
        bool act = true;
        if (qlen) act = t < qlen[m / cfg::NC];
        if (!act) { hn = hprev[off]; cn = co; }
        hnext[off] = hn;
        cnext[off] = cn;
    }
}

// ---------------------------------------------------------------------------
// Small helper kernels
// ---------------------------------------------------------------------------
__global__ void pad_w_k(const float* __restrict__ src, float* __restrict__ dst) {
    int i = blockIdx.x * 256 + threadIdx.x;
    if (i >= cfg::G4 * cfg::EP) return;
    int n = i / cfg::EP, k = i - n * cfg::EP;
    dst[i] = (k < cfg::E) ? src[(size_t)n * cfg::E + k] : 0.f;
}

__global__ void embed_gather_k(const int* __restrict__ q, const float* __restrict__ emb,
                               float* __restrict__ dst) {
    int i = blockIdx.x * 256 + threadIdx.x;
    if (i >= cfg::MT * cfg::L * cfg::EP) return;
    int r = i / cfg::EP, k = i - r * cfg::EP;   // r = m*20 + t
    dst[i] = (k < cfg::E) ? emb[(size_t)q[r] * cfg::E + k] : 0.f;
}

__global__ void zero_k(float* __restrict__ p, int n) {
    int i = blockIdx.x * 256 + threadIdx.x;
    if (i < n) p[i] = 0.f;
}

__global__ void bcast_states_k(const float* __restrict__ vs, float* __restrict__ ts) {
    int i = blockIdx.x * 256 + threadIdx.x;
    if (i >= 4 * cfg::MH) return;
    int a = i / cfg::MH;
    int r = i - a * cfg::MH;
    int m = r / cfg::H, jj = r - m * cfg::H;
    ts[i] = vs[(size_t)a * cfg::BH + (size_t)(m / cfg::NC) * cfg::H + jj];
}

__global__ void concat_k(const float* __restrict__ h1, const float* __restrict__ h2,
                         float* __restrict__ st) {
    int i = blockIdx.x * 256 + threadIdx.x;
    if (i >= cfg::MT * 2 * cfg::H) return;
    int m = i / (2 * cfg::H), jj = i - m * 2 * cfg::H;
    st[i] = (jj < cfg::H) ? h1[(size_t)m * cfg::H + jj]
                          : h2[(size_t)m * cfg::H + (jj - cfg::H)];
}

__global__ void rowdot_k(const float* __restrict__ fe, const float* __restrict__ w,
                         const float* __restrict__ b, float* __restrict__ out) {
    int warp = (blockIdx.x * blockDim.x + threadIdx.x) >> 5;
    int lane = threadIdx.x & 31;
    if (warp >= cfg::MT) return;
    const float* row = fe + (size_t)warp * (2 * cfg::H);
    float s = 0.f;
    for (int k = lane; k < 2 * cfg::H; k += 32) s += row[k] * w[k];
#pragma unroll
    for (int o = 16; o; o >>= 1) s += __shfl_xor_sync(0xffffffffu, s, o);
    if (lane == 0) out[warp] = s + b[0];
}

// d_out layout: outputs[320] then predictions[64] as float; tail zero.
__global__ void finalize_k(const float* __restrict__ outv, float* __restrict__ dout,
                           int out_size) {
    int i = blockIdx.x * 256 + threadIdx.x;
    if (i >= out_size) return;
    if (i < cfg::MT) {
        dout[i] = outv[i];
    } else if (i < cfg::MT + cfg::B) {
        int b = i - cfg::MT;
        float best = outv[b * cfg::NC]; int bi = 0;
#pragma unroll
        for (int nc = 1; nc < cfg::NC; nc++) {
            float v = outv[b * cfg::NC + nc];
            if (v > best) { best = v; bi = nc; }
        }
        dout[i] = (float)bi;
    } else {
        dout[i] = 0.f;
    }
}

// ---------------------------------------------------------------------------
// Host launcher (graph-capturable: kernel launches only)
// ---------------------------------------------------------------------------
extern "C" void kernel_launch(void* const* d_in, const int* in_sizes, int n_in,
                              void* d_out, int out_size) {
    using namespace cfg;
    const float* vf       = (const float*)d_in[0];
    const int*   questions= (const int*)  d_in[1];
    const int*   qlen     = (const int*)  d_in[2];
    const float* embw     = (const float*)d_in[3];
    const float* Wih_t1   = (const float*)d_in[4];
    const float* Whh_t1   = (const float*)d_in[5];
    const float* b_t1     = (const float*)d_in[6];
    const float* Wih_t2   = (const float*)d_in[7];
    const float* Whh_t2   = (const float*)d_in[8];
    const float* b_t2     = (const float*)d_in[9];
    const float* Wih_v1   = (const float*)d_in[10];
    const float* Whh_v1   = (const float*)d_in[11];
    const float* b_v1     = (const float*)d_in[12];
    const float* Wih_v2   = (const float*)d_in[13];
    const float* Whh_v2   = (const float*)d_in[14];
    const float* b_v2     = (const float*)d_in[15];
    const float* dec1_w   = (const float*)d_in[16];
    const float* dec1_b   = (const float*)d_in[17];
    const float* dec2_w   = (const float*)d_in[18];
    const float* dec2_b   = (const float*)d_in[19];
    (void)in_sizes; (void)n_in;

    float* S = nullptr;
    cudaGetSymbolAddress((void**)&S, g_scratch);
    float* GV   = S + OFF_GV;
    float* GT   = S + OFF_GT;
    float* XT   = S + OFF_XT;
    float* WT1P = S + OFF_WT1P;
    float* VS0  = S + OFF_VS0;
    float* VS1  = S + OFF_VS1;
    float* VRAW = S + OFF_VRAW;
    float* TS0  = S + OFF_TS0;
    float* TS1  = S + OFF_TS1;
    float* TRAW = S + OFF_TRAW;
    float* ST   = S + OFF_ST;
    float* FE   = S + OFF_FE;
    float* OUTV = S + OFF_OUT;
    float* dout = (float*)d_out;

    // Stage padded weight + gathered/padded embeddings
    pad_w_k<<<(G4 * EP + 255) / 256, 256>>>(Wih_t1, WT1P);
    embed_gather_k<<<(MT * L * EP + 255) / 256, 256>>>(questions, embw, XT);

    // Big time-parallel input-gate GEMMs
    gemm_tn<<<dim3(G4 / 128, (B * F) / 128), 256>>>(vf, Wih_v1, b_v1, GV, B * F, G4, C);
    gemm_tn<<<dim3(G4 / 128, (MT * L) / 128), 256>>>(XT, WT1P, b_t1, GT, MT * L, G4, EP);

    // Video recurrence (zero init states)
    zero_k<<<(4 * BH + 255) / 256, 256>>>(VS0, 4 * BH);
    for (int t = 0; t < F; t++) {
        float* cur = (t & 1) ? VS1 : VS0;
        float* nxt = (t & 1) ? VS0 : VS1;
        lstm_step<1, false><<<dim3(32, 4), 256>>>(
            cur, Whh_v1, nullptr, nullptr, GV, nullptr, t, F,
            cur, cur + BH, nxt, nxt + BH, VRAW, nullptr, B);
        lstm_step<1, true><<<dim3(32, 4), 256>>>(
            VRAW, Wih_v2, cur + 2 * BH, Whh_v2, nullptr, b_v2, t, F,
            cur + 2 * BH, cur + 3 * BH, nxt + 2 * BH, nxt + 3 * BH, nullptr,
            nullptr, B);
    }

    // Seed text states from final video state (20 steps even -> VS0)
    bcast_states_k<<<(4 * MH + 255) / 256, 256>>>(VS0, TS0);

    // Text recurrence with ragged mask
    for (int t = 0; t < L; t++) {
        float* cur = (t & 1) ? TS1 : TS0;
        float* nxt = (t & 1) ? TS0 : TS1;
        lstm_step<4, false><<<dim3(32, 5), 256>>>(
            cur, Whh_t1, nullptr, nullptr, GT, nullptr, t, L,
            cur, cur + MH, nxt, nxt + MH, TRAW, qlen, MT);
        lstm_step<4, true><<<dim3(32, 5), 256>>>(
            TRAW, Wih_t2, cur + 2 * MH, Whh_t2, nullptr, b_t2, t, L,
            cur + 2 * MH, cur + 3 * MH, nxt + 2 * MH, nxt + 3 * MH, nullptr,
            qlen, MT);
    }

    // Decoder
    concat_k<<<(MT * 2 * H + 255) / 256, 256>>>(TS0, TS0 + 2 * MH, ST);
    gemm_tn<<<dim3((2 * H) / 128, (MT + 127) / 128), 256>>>(ST, dec1_w, dec1_b, FE,
                                                            MT, 2 * H, 2 * H);
    rowdot_k<<<40, 256>>>(FE, dec2_w, dec2_b, OUTV);
    finalize_k<<<(out_size + 255) / 256, 256>>>(OUTV, dout, out_size);
}

// round 3
// speedup vs baseline: 1.7132x; 1.1571x over previous
#include <cuda_runtime.h>
#include <math.h>
#include <stdint.h>

// ---------------------------------------------------------------------------
// LSTMEncDec — R3: all large GEMMs (input-projection precompute + recurrence
// steps) on tensor cores via mma.sync m16n8k8 tf32 with 3xTF32 error
// compensation (fp32-level accuracy). cp.async double-buffered pipelines.
// ---------------------------------------------------------------------------

namespace cfg {
constexpr int B = 64, NC = 5, L = 20, F = 20, C = 8192, E = 300;
constexpr int H = 512, G4 = 2048, V = 8000;
constexpr int MT = B * NC;           // 320 text rows
constexpr int EP = 320;              // E padded to %16==0 for BK chunking
constexpr int BH = B * H;            // 32768
constexpr int MH = MT * H;           // 163840

constexpr size_t OFF_GV   = 0;                                    // [B*F, G4]
constexpr size_t OFF_GT   = OFF_GV   + (size_t)B * F * G4;        // [MT*L, G4]
constexpr size_t OFF_XT   = OFF_GT   + (size_t)MT * L * G4;       // [MT*L, EP]
constexpr size_t OFF_WT1P = OFF_XT   + (size_t)MT * L * EP;       // [G4, EP]
constexpr size_t OFF_VS0  = OFF_WT1P + (size_t)G4 * EP;           // vh1,vc1,vh2,vc2
constexpr size_t OFF_VS1  = OFF_VS0  + 4ull * BH;
constexpr size_t OFF_VRAW = OFF_VS1  + 4ull * BH;
constexpr size_t OFF_TS0  = OFF_VRAW + (size_t)BH;                // th1,tc1,th2,tc2
constexpr size_t OFF_TS1  = OFF_TS0  + 4ull * MH;
constexpr size_t OFF_TRAW = OFF_TS1  + 4ull * MH;
constexpr size_t OFF_ST   = OFF_TRAW + (size_t)MH;                // [MT, 2H]
constexpr size_t OFF_FE   = OFF_ST   + (size_t)MT * 2 * H;        // [MT, 2H]
constexpr size_t OFF_OUT  = OFF_FE   + (size_t)MT * 2 * H;        // [MT]
constexpr size_t TOTAL    = OFF_OUT  + (size_t)MT;
}  // namespace cfg

__device__ __align__(256) float g_scratch[cfg::TOTAL];

__device__ __forceinline__ float sigm(float x) { return 1.f / (1.f + expf(-x)); }

// ---------------------------------------------------------------------------
// Tensor-core primitives
// ---------------------------------------------------------------------------
__device__ __forceinline__ void cp_async16(void* smem, const void* gmem) {
    uint32_t s = (uint32_t)__cvta_generic_to_shared(smem);
    asm volatile("cp.async.cg.shared.global [%0], [%1], 16;\n" :: "r"(s), "l"(gmem));
}
#define CP_COMMIT asm volatile("cp.async.commit_group;\n" ::: "memory")
#define CP_WAIT0  asm volatile("cp.async.wait_group 0;\n" ::: "memory")

// 3xTF32 split: hi = x with low 13 mantissa bits cleared (exact tf32),
// lo = x - hi (fits tf32 up to ~3 guard bits; residual error ~2^-21 rel).
__device__ __forceinline__ void split_tf32(float x, uint32_t& hi, uint32_t& lo) {
    uint32_t xh = __float_as_uint(x) & 0xFFFFE000u;
    hi = xh;
    lo = __float_as_uint(x - __uint_as_float(xh));
}

// D(16x8) += A(16x8) * B(8x8), row.col, tf32 in / f32 accum
__device__ __forceinline__ void mma8(float* c, const uint32_t* a, uint32_t b0, uint32_t b1) {
    asm volatile(
        "mma.sync.aligned.m16n8k8.row.col.f32.tf32.tf32.f32 "
        "{%0,%1,%2,%3}, {%4,%5,%6,%7}, {%8,%9}, {%0,%1,%2,%3};"
        : "+f"(c[0]), "+f"(c[1]), "+f"(c[2]), "+f"(c[3])
        : "r"(a[0]), "r"(a[1]), "r"(a[2]), "r"(a[3]), "r"(b0), "r"(b1));
}

// ---------------------------------------------------------------------------
// Tensor-core TN GEMM: C[M,N] = A[M,K] @ W[N,K]^T (+bias). 3xTF32.
// 256 threads, block tile 128x128, BK=16, double-buffered cp.async.
// Warp grid 2(m) x 4(n): warp tile 64x32. Requires M%128==0, N%128==0, K%16==0.
// ---------------------------------------------------------------------------
__global__ void __launch_bounds__(256) gemm_tc(
    const float* __restrict__ A, const float* __restrict__ W,
    const float* __restrict__ bias, float* __restrict__ Cmat,
    int M, int N, int K)
{
    constexpr int BK = 16;
    __shared__ float sA[2][128][BK + 4];
    __shared__ float sW[2][128][BK + 4];
    const int tid = threadIdx.x;
    const int lane = tid & 31, warp = tid >> 5;
    const int wm = warp & 1, wn = warp >> 1;
    const int g = lane >> 2, t4 = lane & 3;
    const int bm = blockIdx.y * 128, bn = blockIdx.x * 128;

    float acc[4][4][4] = {};

    const int NCH = K / BK;
    auto issue = [&](int c, int buf) {
#pragma unroll
        for (int q = 0; q < 2; q++) {
            int v = tid + q * 256;
            int r = v >> 2, k4 = (v & 3) << 2;
            cp_async16(&sA[buf][r][k4], A + (size_t)(bm + r) * K + c * BK + k4);
            cp_async16(&sW[buf][r][k4], W + (size_t)(bn + r) * K + c * BK + k4);
        }
    };

    issue(0, 0); CP_COMMIT;
    for (int c = 0; c < NCH; c++) {
        const int buf = c & 1;
        CP_WAIT0;
        __syncthreads();
        if (c + 1 < NCH) { issue(c + 1, buf ^ 1); CP_COMMIT; }
#pragma unroll
        for (int kk = 0; kk < 2; kk++) {
            const int k0 = kk * 8;
            uint32_t ahi[4][4], alo[4][4];
#pragma unroll
            for (int mt = 0; mt < 4; mt++) {
                int r = wm * 64 + mt * 16 + g;
                split_tf32(sA[buf][r][k0 + t4],         ahi[mt][0], alo[mt][0]);
                split_tf32(sA[buf][r + 8][k0 + t4],     ahi[mt][1], alo[mt][1]);
                split_tf32(sA[buf][r][k0 + t4 + 4],     ahi[mt][2], alo[mt][2]);
                split_tf32(sA[buf][r + 8][k0 + t4 + 4], ahi[mt][3], alo[mt][3]);
            }
#pragma unroll
            for (int nt = 0; nt < 4; nt++) {
                int n = wn * 32 + nt * 8 + g;
                uint32_t bh0, bl0, bh1, bl1;
                split_tf32(sW[buf][n][k0 + t4],     bh0, bl0);
                split_tf32(sW[buf][n][k0 + t4 + 4], bh1, bl1);
#pragma unroll
                for (int mt = 0; mt < 4; mt++) {
                    mma8(acc[mt][nt], ahi[mt], bh0, bh1);
                    mma8(acc[mt][nt], ahi[mt], bl0, bl1);
                    mma8(acc[mt][nt], alo[mt], bh0, bh1);
                }
            }
        }
        __syncthreads();
    }

#pragma unroll
    for (int mt = 0; mt < 4; mt++) {
#pragma unroll
        for (int rr = 0; rr < 2; rr++) {
            int m = bm + wm * 64 + mt * 16 + g + rr * 8;
#pragma unroll
            for (int nt = 0; nt < 4; nt++) {
                int n = bn + wn * 32 + nt * 8 + t4 * 2;
                float v0 = acc[mt][nt][rr * 2 + 0];
                float v1 = acc[mt][nt][rr * 2 + 1];
                if (bias) { v0 += bias[n]; v1 += bias[n + 1]; }
                *(float2*)(Cmat + (size_t)m * N + n) = make_float2(v0, v1);
            }
        }
    }
}

// ---------------------------------------------------------------------------
// Tensor-core fused LSTM step. Block: 128 threads (4 warps), tile:
// 64 rows (warp = 16) x 16 hidden cols x all 4 gates. K=512 (L1) or
// 1024=2x512 (L2: x@Wih then h@Whh). 3xTF32, cp.async double-buffered.
//   L1: gates = Gpre[(m*Tsteps+t)*2048 + gcol] + h@Whh^T   (writes hraw too)
//   L2: gates = bias[gcol] + x@Wih^T + h@Whh^T
// Requires M % 64 == 0.
// ---------------------------------------------------------------------------
template <bool L2K>
__global__ void __launch_bounds__(128) lstm_step_tc(
    const float* __restrict__ src0, const float* __restrict__ W0,
    const float* __restrict__ src1, const float* __restrict__ W1,
    const float* __restrict__ Gpre, const float* __restrict__ bias,
    int t, int Tsteps,
    const float* __restrict__ hprev, const float* __restrict__ cprev,
    float* __restrict__ hnext, float* __restrict__ cnext,
    float* __restrict__ hraw,
    const int* __restrict__ qlen)
{
    constexpr int BK = 16;
    constexpr int NCH = L2K ? 64 : 32;
    __shared__ float sH[2][64][BK + 4];
    __shared__ float sW[2][64][BK + 4];
    const int tid = threadIdx.x;
    const int lane = tid & 31, warp = tid >> 5;
    const int g = lane >> 2, t4 = lane & 3;
    const int j0 = blockIdx.x * 16;
    const int m0 = blockIdx.y * 64;

    float acc[4][2][4] = {};   // [gate][ntile][frag]

    auto issue = [&](int c, int buf) {
        const float* s = src0;
        const float* Wm = W0;
        int kpos = c * BK;
        if (L2K && c >= 32) { s = src1; Wm = W1; kpos -= 512; }
#pragma unroll
        for (int q = 0; q < 2; q++) {
            int v = tid + q * 128;
            int r = v >> 2, k4 = (v & 3) << 2;
            cp_async16(&sH[buf][r][k4], s + (size_t)(m0 + r) * 512 + kpos + k4);
            int gc = (r >> 4) * 512 + j0 + (r & 15);
            cp_async16(&sW[buf][r][k4], Wm + (size_t)gc * 512 + kpos + k4);
        }
    };

    issue(0, 0); CP_COMMIT;
    for (int c = 0; c < NCH; c++) {
        const int buf = c & 1;
        CP_WAIT0;
        __syncthreads();
        if (c + 1 < NCH) { issue(c + 1, buf ^ 1); CP_COMMIT; }
#pragma unroll
        for (int kk = 0; kk < 2; kk++) {
            const int k0 = kk * 8;
            uint32_t ahi[4], alo[4];
            const int r = warp * 16 + g;
            split_tf32(sH[buf][r][k0 + t4],         ahi[0], alo[0]);
            split_tf32(sH[buf][r + 8][k0 + t4],     ahi[1], alo[1]);
            split_tf32(sH[buf][r][k0 + t4 + 4],     ahi[2], alo[2]);
            split_tf32(sH[buf][r + 8][k0 + t4 + 4], ahi[3], alo[3]);
#pragma unroll
            for (int gg = 0; gg < 4; gg++)
#pragma unroll
                for (int nt = 0; nt < 2; nt++) {
                    int n = gg * 16 + nt * 8 + g;
                    uint32_t bh0, bl0, bh1, bl1;
                    split_tf32(sW[buf][n][k0 + t4],     bh0, bl0);
                    split_tf32(sW[buf][n][k0 + t4 + 4], bh1, bl1);
                    mma8(acc[gg][nt], ahi, bh0, bh1);
                    mma8(acc[gg][nt], ahi, bl0, bl1);
                    mma8(acc[gg][nt], alo, bh0, bh1);
                }
        }
        __syncthreads();
    }

    // Epilogue: this thread owns rows {m0+warp*16+g, +8} x cols {j0+t4*2+nt*8, +1}
    const int jb = j0 + t4 * 2;
#pragma unroll
    for (int rr = 0; rr < 2; rr++) {
        const int m = m0 + warp * 16 + g + rr * 8;
        bool act = true;
        if (qlen) act = t < qlen[m / cfg::NC];
        const float* gp = L2K ? bias : (Gpre + ((size_t)m * Tsteps + t) * 2048);
#pragma unroll
        for (int nt = 0; nt < 2; nt++) {
            const int j = jb + nt * 8;
            float2 bi = *(const float2*)(gp + j);
            float2 bf = *(const float2*)(gp + 512 + j);
            float2 bg = *(const float2*)(gp + 1024 + j);
            float2 bo = *(const float2*)(gp + 1536 + j);
            const size_t off = (size_t)m * 512 + j;
            float2 co = *(const float2*)(cprev + off);
            float gi0 = acc[0][nt][rr * 2 + 0] + bi.x;
            float gi1 = acc[0][nt][rr * 2 + 1] + bi.y;
            float gf0 = acc[1][nt][rr * 2 + 0] + bf.x;
            float gf1 = acc[1][nt][rr * 2 + 1] + bf.y;
            float gg0 = acc[2][nt][rr * 2 + 0] + bg.x;
            float gg1 = acc[2][nt][rr * 2 + 1] + bg.y;
            float go0 = acc[3][nt][rr * 2 + 0] + bo.x;
            float go1 = acc[3][nt][rr * 2 + 1] + bo.y;
            float cn0 = sigm(gf0) * co.x + sigm(gi0) * tanhf(gg0);
            float cn1 = sigm(gf1) * co.y + sigm(gi1) * tanhf(gg1);
            float hn0 = sigm(go0) * tanhf(cn0);
            float hn1 = sigm(go1) * tanhf(cn1);
            if (!L2K) *(float2*)(hraw + off) = make_float2(hn0, hn1);
            if (!act) {
                float2 hp = *(const float2*)(hprev + off);
                hn0 = hp.x; hn1 = hp.y; cn0 = co.x; cn1 = co.y;
            }
            *(float2*)(hnext + off) = make_float2(hn0, hn1);
            *(float2*)(cnext + off) = make_float2(cn0, cn1);
        }
    }
}

// ---------------------------------------------------------------------------
// SIMT GEMM kept for the small decoder matmul (M=320 not %128).
// ---------------------------------------------------------------------------
__global__ void __launch_bounds__(256) gemm_tn(
    const float* __restrict__ A, const float* __restrict__ W,
    const float* __restrict__ bias, float* __restrict__ Cmat,
    int M, int N, int K)
{
    __shared__ float sA[8][128];
    __shared__ float sB[8][128];
    const int tid = threadIdx.x;
    const int tx = tid & 15, ty = tid >> 4;
    const int bm = blockIdx.y * 128, bn = blockIdx.x * 128;
    const int lr = tid >> 1;
    const int lk = (tid & 1) << 2;
    const bool aok = (bm + lr) < M;
    const float* Arow = A + (size_t)(bm + lr) * K + lk;
    const float* Wrow = W + (size_t)(bn + lr) * K + lk;

    float acc[8][8] = {};

    for (int k0 = 0; k0 < K; k0 += 8) {
        float4 av = aok ? *(const float4*)(Arow + k0) : make_float4(0.f, 0.f, 0.f, 0.f);
        float4 wv = *(const float4*)(Wrow + k0);
        __syncthreads();
        sA[lk + 0][lr] = av.x; sA[lk + 1][lr] = av.y;
        sA[lk + 2][lr] = av.z; sA[lk + 3][lr] = av.w;
        sB[lk + 0][lr] = wv.x; sB[lk + 1][lr] = wv.y;
        sB[lk + 2][lr] = wv.z; sB[lk + 3][lr] = wv.w;
        __syncthreads();
#pragma unroll
        for (int kk = 0; kk < 8; kk++) {
            float4 a0 = *(const float4*)&sA[kk][ty * 4];
            float4 a1 = *(const float4*)&sA[kk][64 + ty * 4];
            float4 b0 = *(const float4*)&sB[kk][tx * 4];
            float4 b1 = *(const float4*)&sB[kk][64 + tx * 4];
            float af[8] = {a0.x, a0.y, a0.z, a0.w, a1.x, a1.y, a1.z, a1.w};
            float bf[8] = {b0.x, b0.y, b0.z, b0.w, b1.x, b1.y, b1.z, b1.w};
#pragma unroll
            for (int i = 0; i < 8; i++)
#pragma unroll
                for (int j = 0; j < 8; j++)
                    acc[i][j] += af[i] * bf[j];
        }
    }

#pragma unroll
    for (int i = 0; i < 8; i++) {
        int m = bm + (i < 4 ? ty * 4 + i : 64 + ty * 4 + (i - 4));
        if (m >= M) continue;
#pragma unroll
        for (int j = 0; j < 8; j++) {
            int n = bn + (j < 4 ? tx * 4 + j : 64 + tx * 4 + (j - 4));
            float v = acc[i][j];
            if (bias) v += bias[n];
            Cmat[(size_t)m * N + n] = v;
        }
    }
}

// ---------------------------------------------------------------------------
// Small helper kernels
// ---------------------------------------------------------------------------
__global__ void pad_w_k(const float* __restrict__ src, float* __restrict__ dst) {
    int i = blockIdx.x * 256 + threadIdx.x;
    if (i >= cfg::G4 * cfg::EP) return;
    int n = i / cfg::EP, k = i - n * cfg::EP;
    dst[i] = (k < cfg::E) ? src[(size_t)n * cfg::E + k] : 0.f;
}

__global__ void embed_gather_k(const int* __restrict__ q, const float* __restrict__ emb,
                               float* __restrict__ dst) {
    int i = blockIdx.x * 256 + threadIdx.x;
    if (i >= cfg::MT * cfg::L * cfg::EP) return;
    int r = i / cfg::EP, k = i - r * cfg::EP;   // r = m*20 + t
    dst[i] = (k < cfg::E) ? emb[(size_t)q[r] * cfg::E + k] : 0.f;
}

__global__ void zero_k(float* __restrict__ p, int n) {
    int i = blockIdx.x * 256 + threadIdx.x;
    if (i < n) p[i] = 0.f;
}

__global__ void bcast_states_k(const float* __restrict__ vs, float* __restrict__ ts) {
    int i = blockIdx.x * 256 + threadIdx.x;
    if (i >= 4 * cfg::MH) return;
    int a = i / cfg::MH;
    int r = i - a * cfg::MH;
    int m = r / cfg::H, jj = r - m * cfg::H;
    ts[i] = vs[(size_t)a * cfg::BH + (size_t)(m / cfg::NC) * cfg::H + jj];
}

__global__ void concat_k(const float* __restrict__ h1, const float* __restrict__ h2,
                         float* __restrict__ st) {
    int i = blockIdx.x * 256 + threadIdx.x;
    if (i >= cfg::MT * 2 * cfg::H) return;
    int m = i / (2 * cfg::H), jj = i - m * 2 * cfg::H;
    st[i] = (jj < cfg::H) ? h1[(size_t)m * cfg::H + jj]
                          : h2[(size_t)m * cfg::H + (jj - cfg::H)];
}

__global__ void rowdot_k(const float* __restrict__ fe, const float* __restrict__ w,
                         const float* __restrict__ b, float* __restrict__ out) {
    int warp = (blockIdx.x * blockDim.x + threadIdx.x) >> 5;
    int lane = threadIdx.x & 31;
    if (warp >= cfg::MT) return;
    const float* row = fe + (size_t)warp * (2 * cfg::H);
    float s = 0.f;
    for (int k = lane; k < 2 * cfg::H; k += 32) s += row[k] * w[k];
#pragma unroll
    for (int o = 16; o; o >>= 1) s += __shfl_xor_sync(0xffffffffu, s, o);
    if (lane == 0) out[warp] = s + b[0];
}

// d_out layout: outputs[320] then predictions[64] as float; tail zero.
__global__ void finalize_k(const float* __restrict__ outv, float* __restrict__ dout,
                           int out_size) {
    int i = blockIdx.x * 256 + threadIdx.x;
    if (i >= out_size) return;
    if (i < cfg::MT) {
        dout[i] = outv[i];
    } else if (i < cfg::MT + cfg::B) {
        int b = i - cfg::MT;
        float best = outv[b * cfg::NC]; int bi = 0;
#pragma unroll
        for (int nc = 1; nc < cfg::NC; nc++) {
            float v = outv[b * cfg::NC + nc];
            if (v > best) { best = v; bi = nc; }
        }
        dout[i] = (float)bi;
    } else {
        dout[i] = 0.f;
    }
}

// ---------------------------------------------------------------------------
// Host launcher (graph-capturable: kernel launches only)
// ---------------------------------------------------------------------------
extern "C" void kernel_launch(void* const* d_in, const int* in_sizes, int n_in,
                              void* d_out, int out_size) {
    using namespace cfg;
    const float* vf       = (const float*)d_in[0];
    const int*   questions= (const int*)  d_in[1];
    const int*   qlen     = (const int*)  d_in[2];
    const float* embw     = (const float*)d_in[3];
    const float* Wih_t1   = (const float*)d_in[4];
    const float* Whh_t1   = (const float*)d_in[5];
    const float* b_t1     = (const float*)d_in[6];
    const float* Wih_t2   = (const float*)d_in[7];
    const float* Whh_t2   = (const float*)d_in[8];
    const float* b_t2     = (const float*)d_in[9];
    const float* Wih_v1   = (const float*)d_in[10];
    const float* Whh_v1   = (const float*)d_in[11];
    const float* b_v1     = (const float*)d_in[12];
    const float* Wih_v2   = (const float*)d_in[13];
    const float* Whh_v2   = (const float*)d_in[14];
    const float* b_v2     = (const float*)d_in[15];
    const float* dec1_w   = (const float*)d_in[16];
    const float* dec1_b   = (const float*)d_in[17];
    const float* dec2_w   = (const float*)d_in[18];
    const float* dec2_b   = (const float*)d_in[19];
    (void)in_sizes; (void)n_in;

    float* S = nullptr;
    cudaGetSymbolAddress((void**)&S, g_scratch);
    float* GV   = S + OFF_GV;
    float* GT   = S + OFF_GT;
    float* XT   = S + OFF_XT;
    float* WT1P = S + OFF_WT1P;
    float* VS0  = S + OFF_VS0;
    float* VS1  = S + OFF_VS1;
    float* VRAW = S + OFF_VRAW;
    float* TS0  = S + OFF_TS0;
    float* TS1  = S + OFF_TS1;
    float* TRAW = S + OFF_TRAW;
    float* ST   = S + OFF_ST;
    float* FE   = S + OFF_FE;
    float* OUTV = S + OFF_OUT;
    float* dout = (float*)d_out;

    // Stage padded weight + gathered/padded embeddings
    pad_w_k<<<(G4 * EP + 255) / 256, 256>>>(Wih_t1, WT1P);
    embed_gather_k<<<(MT * L * EP + 255) / 256, 256>>>(questions, embw, XT);

    // Big time-parallel input-gate GEMMs on tensor cores
    gemm_tc<<<dim3(G4 / 128, (B * F) / 128), 256>>>(vf, Wih_v1, b_v1, GV, B * F, G4, C);
    gemm_tc<<<dim3(G4 / 128, (MT * L) / 128), 256>>>(XT, WT1P, b_t1, GT, MT * L, G4, EP);

    // Video recurrence (zero init states)
    zero_k<<<(4 * BH + 255) / 256, 256>>>(VS0, 4 * BH);
    for (int t = 0; t < F; t++) {
        float* cur = (t & 1) ? VS1 : VS0;
        float* nxt = (t & 1) ? VS0 : VS1;
        lstm_step_tc<false><<<dim3(32, B / 64), 128>>>(
            cur, Whh_v1, nullptr, nullptr, GV, nullptr, t, F,
            cur, cur + BH, nxt, nxt + BH, VRAW, nullptr);
        lstm_step_tc<true><<<dim3(32, B / 64), 128>>>(
            VRAW, Wih_v2, cur + 2 * BH, Whh_v2, nullptr, b_v2, t, F,
            cur + 2 * BH, cur + 3 * BH, nxt + 2 * BH, nxt + 3 * BH, nullptr,
            nullptr);
    }

    // Seed text states from final video state (20 steps even -> VS0)
    bcast_states_k<<<(4 * MH + 255) / 256, 256>>>(VS0, TS0);

    // Text recurrence with ragged mask
    for (int t = 0; t < L; t++) {
        float* cur = (t & 1) ? TS1 : TS0;
        float* nxt = (t & 1) ? TS0 : TS1;
        lstm_step_tc<false><<<dim3(32, MT / 64), 128>>>(
            cur, Whh_t1, nullptr, nullptr, GT, nullptr, t, L,
            cur, cur + MH, nxt, nxt + MH, TRAW, qlen);
        lstm_step_tc<true><<<dim3(32, MT / 64), 128>>>(
            TRAW, Wih_t2, cur + 2 * MH, Whh_t2, nullptr, b_t2, t, L,
            cur + 2 * MH, cur + 3 * MH, nxt + 2 * MH, nxt + 3 * MH, nullptr,
            qlen);
    }

    // Decoder
    concat_k<<<(MT * 2 * H + 255) / 256, 256>>>(TS0, TS0 + 2 * MH, ST);
    gemm_tn<<<dim3((2 * H) / 128, (MT + 127) / 128), 256>>>(ST, dec1_w, dec1_b, FE,
                                                            MT, 2 * H, 2 * H);
    rowdot_k<<<40, 256>>>(FE, dec2_w, dec2_b, OUTV);
    finalize_k<<<(out_size + 255) / 256, 256>>>(OUTV, dout, out_size);
}

// round 4
// speedup vs baseline: 2.4182x; 1.4115x over previous
#include <cuda_runtime.h>
#include <math.h>
#include <stdint.h>

// ---------------------------------------------------------------------------
// LSTMEncDec — R4: single persistent kernel for the whole recurrence (grid
// barriers replace 80 launches), distance-2 cp.async prefetch everywhere,
// 64x128 tensor GEMM tiles, decoder GEMM on tensor cores too. 3xTF32.
// ---------------------------------------------------------------------------

namespace cfg {
constexpr int B = 64, NC = 5, L = 20, F = 20, C = 8192, E = 300;
constexpr int H = 512, G4 = 2048, V = 8000;
constexpr int MT = B * NC;           // 320 text rows
constexpr int EP = 320;              // E padded to %16==0
constexpr int BH = B * H;            // 32768
constexpr int MH = MT * H;           // 163840
constexpr int NBLK = 320;            // persistent grid

constexpr size_t OFF_GV   = 0;                                    // [B*F, G4]
constexpr size_t OFF_GT   = OFF_GV   + (size_t)B * F * G4;        // [MT*L, G4]
constexpr size_t OFF_XT   = OFF_GT   + (size_t)MT * L * G4;       // [MT*L, EP]
constexpr size_t OFF_WT1P = OFF_XT   + (size_t)MT * L * EP;       // [G4, EP]
constexpr size_t OFF_VS0  = OFF_WT1P + (size_t)G4 * EP;           // vh1,vc1,vh2,vc2
constexpr size_t OFF_VS1  = OFF_VS0  + 4ull * BH;
constexpr size_t OFF_VRAW = OFF_VS1  + 4ull * BH;
constexpr size_t OFF_TS0  = OFF_VRAW + (size_t)BH;                // th1,tc1,th2,tc2
constexpr size_t OFF_TS1  = OFF_TS0  + 4ull * MH;
constexpr size_t OFF_TRAW = OFF_TS1  + 4ull * MH;
constexpr size_t OFF_ST   = OFF_TRAW + (size_t)MH;                // [MT, 2H]
constexpr size_t OFF_FE   = OFF_ST   + (size_t)MT * 2 * H;        // [MT, 2H]
constexpr size_t OFF_OUT  = OFF_FE   + (size_t)MT * 2 * H;        // [MT]
constexpr size_t TOTAL    = OFF_OUT  + (size_t)MT;
}  // namespace cfg

__device__ __align__(256) float g_scratch[cfg::TOTAL];
__device__ unsigned g_bars[128];

__device__ __forceinline__ float sigm(float x) { return 1.f / (1.f + expf(-x)); }

// ---------------------------------------------------------------------------
// Tensor-core primitives
// ---------------------------------------------------------------------------
__device__ __forceinline__ void cp_async16(void* smem, const void* gmem) {
    uint32_t s = (uint32_t)__cvta_generic_to_shared(smem);
    asm volatile("cp.async.cg.shared.global [%0], [%1], 16;\n" :: "r"(s), "l"(gmem));
}
#define CP_COMMIT asm volatile("cp.async.commit_group;\n" ::: "memory")
#define CP_WAIT0  asm volatile("cp.async.wait_group 0;\n" ::: "memory")
#define CP_WAIT1  asm volatile("cp.async.wait_group 1;\n" ::: "memory")

__device__ __forceinline__ void split_tf32(float x, uint32_t& hi, uint32_t& lo) {
    uint32_t xh = __float_as_uint(x) & 0xFFFFE000u;
    hi = xh;
    lo = __float_as_uint(x - __uint_as_float(xh));
}

__device__ __forceinline__ void mma8(float* c, const uint32_t* a, uint32_t b0, uint32_t b1) {
    asm volatile(
        "mma.sync.aligned.m16n8k8.row.col.f32.tf32.tf32.f32 "
        "{%0,%1,%2,%3}, {%4,%5,%6,%7}, {%8,%9}, {%0,%1,%2,%3};"
        : "+f"(c[0]), "+f"(c[1]), "+f"(c[2]), "+f"(c[3])
        : "r"(a[0]), "r"(a[1]), "r"(a[2]), "r"(a[3]), "r"(b0), "r"(b1));
}

// Grid-wide barrier; counters zeroed by zero_bars_k before each launch.
__device__ __forceinline__ void gridbar(int idx) {
    __syncthreads();
    if (threadIdx.x == 0) {
        __threadfence();
        atomicAdd(&g_bars[idx], 1u);
        while (*((volatile unsigned*)&g_bars[idx]) < (unsigned)cfg::NBLK) {}
        __threadfence();
    }
    __syncthreads();
}

// ---------------------------------------------------------------------------
// One LSTM step tile (32 rows x 16 hidden cols x 4 gates) on tensor cores.
// 128 threads, 4 warps in 2(m) x 2(j): warp = 16 rows x 8 jcols x 4 gates.
// BK=16, distance-2 cp.async prefetch. L1: gates = Gpre + h@Whh^T (writes
// hraw). L2: gates = bias + x@Wih^T + h@Whh^T. All state loads via .cg (L2).
// ---------------------------------------------------------------------------
template <bool L2K>
__device__ __forceinline__ void step_tile(
    const float* __restrict__ src0, const float* __restrict__ W0,
    const float* __restrict__ src1, const float* __restrict__ W1,
    const float* __restrict__ gpre_or_bias, int t, int Tsteps,
    const float* __restrict__ hprev, const float* __restrict__ cprev,
    float* __restrict__ hnext, float* __restrict__ cnext,
    float* __restrict__ hraw, const int* __restrict__ qlen,
    int m0, int j0,
    float (*sH)[32][20], float (*sW)[64][20])
{
    const int tid = threadIdx.x;
    const int lane = tid & 31, warp = tid >> 5;
    const int wm = warp & 1, wj = warp >> 1;
    const int g8 = lane >> 2, t4 = lane & 3;
    constexpr int NCH = L2K ? 64 : 32;

    float acc[4][4] = {};

    auto issue = [&](int c, int buf) {
        const float* s = src0;
        const float* Wm = W0;
        int kpos = c * 16;
        if (L2K && c >= 32) { s = src1; Wm = W1; kpos -= 512; }
        {
            int r = tid >> 2, k4 = (tid & 3) << 2;
            cp_async16(&sH[buf][r][k4], s + (size_t)(m0 + r) * 512 + kpos + k4);
        }
#pragma unroll
        for (int q = 0; q < 2; q++) {
            int v = tid + q * 128;
            int r = v >> 2, k4 = (v & 3) << 2;
            int gc = (r >> 4) * 512 + j0 + (r & 15);
            cp_async16(&sW[buf][r][k4], Wm + (size_t)gc * 512 + kpos + k4);
        }
    };

    issue(0, 0); CP_COMMIT;
    issue(1, 1); CP_COMMIT;
    for (int c = 0; c < NCH; c++) {
        if (c < NCH - 1) { CP_WAIT1; } else { CP_WAIT0; }
        __syncthreads();
        const int buf = c & 1;
#pragma unroll
        for (int kk = 0; kk < 2; kk++) {
            const int k0 = kk * 8;
            uint32_t ahi[4], alo[4];
            const int r = wm * 16 + g8;
            split_tf32(sH[buf][r][k0 + t4],         ahi[0], alo[0]);
            split_tf32(sH[buf][r + 8][k0 + t4],     ahi[1], alo[1]);
            split_tf32(sH[buf][r][k0 + t4 + 4],     ahi[2], alo[2]);
            split_tf32(sH[buf][r + 8][k0 + t4 + 4], ahi[3], alo[3]);
#pragma unroll
            for (int gg = 0; gg < 4; gg++) {
                int n = gg * 16 + wj * 8 + g8;
                uint32_t bh0, bl0, bh1, bl1;
                split_tf32(sW[buf][n][k0 + t4],     bh0, bl0);
                split_tf32(sW[buf][n][k0 + t4 + 4], bh1, bl1);
                mma8(acc[gg], ahi, bh0, bh1);
                mma8(acc[gg], ahi, bl0, bl1);
                mma8(acc[gg], alo, bh0, bh1);
            }
        }
        __syncthreads();
        if (c + 2 < NCH) { issue(c + 2, buf); CP_COMMIT; }
    }

    const int jb = j0 + wj * 8 + t4 * 2;
#pragma unroll
    for (int rr = 0; rr < 2; rr++) {
        const int m = m0 + wm * 16 + g8 + rr * 8;
        bool act = true;
        if (qlen) act = t < qlen[m / cfg::NC];
        const float* gp = L2K ? gpre_or_bias
                              : (gpre_or_bias + ((size_t)m * Tsteps + t) * 2048);
        float2 bi = *(const float2*)(gp + jb);
        float2 bf = *(const float2*)(gp + 512 + jb);
        float2 bg = *(const float2*)(gp + 1024 + jb);
        float2 bo = *(const float2*)(gp + 1536 + jb);
        const size_t off = (size_t)m * 512 + jb;
        float2 co = *(const float2*)(cprev + off);
        float gi0 = acc[0][rr * 2 + 0] + bi.x, gi1 = acc[0][rr * 2 + 1] + bi.y;
        float gf0 = acc[1][rr * 2 + 0] + bf.x, gf1 = acc[1][rr * 2 + 1] + bf.y;
        float gg0 = acc[2][rr * 2 + 0] + bg.x, gg1 = acc[2][rr * 2 + 1] + bg.y;
        float go0 = acc[3][rr * 2 + 0] + bo.x, go1 = acc[3][rr * 2 + 1] + bo.y;
        float cn0 = sigm(gf0) * co.x + sigm(gi0) * tanhf(gg0);
        float cn1 = sigm(gf1) * co.y + sigm(gi1) * tanhf(gg1);
        float hn0 = sigm(go0) * tanhf(cn0);
        float hn1 = sigm(go1) * tanhf(cn1);
        if (!L2K) *(float2*)(hraw + off) = make_float2(hn0, hn1);
        if (!act) {
            float2 hp = *(const float2*)(hprev + off);
            hn0 = hp.x; hn1 = hp.y; cn0 = co.x; cn1 = co.y;
        }
        *(float2*)(hnext + off) = make_float2(hn0, hn1);
        *(float2*)(cnext + off) = make_float2(cn0, cn1);
    }
}

// ---------------------------------------------------------------------------
// Persistent recurrence kernel: zero init -> video 20 steps -> broadcast ->
// text 20 steps. 320 blocks x 128 threads; grid barriers between stages.
// ---------------------------------------------------------------------------
__global__ void __launch_bounds__(128, 3) recurrence_k(
    const float* __restrict__ GV, const float* __restrict__ GT,
    const float* __restrict__ Whh_v1, const float* __restrict__ Wih_v2,
    const float* __restrict__ Whh_v2, const float* __restrict__ b_v2,
    const float* __restrict__ Whh_t1, const float* __restrict__ Wih_t2,
    const float* __restrict__ Whh_t2, const float* __restrict__ b_t2,
    const int* __restrict__ qlen,
    float* __restrict__ VS0, float* __restrict__ VS1, float* __restrict__ VRAW,
    float* __restrict__ TS0, float* __restrict__ TS1, float* __restrict__ TRAW)
{
    using namespace cfg;
    __shared__ float sH[2][32][20];
    __shared__ float sW[2][64][20];
    const int blk = blockIdx.x;
    const int gtid = blk * 128 + threadIdx.x;
    int bar = 0;

    // Zero video init states
    for (int i = gtid; i < 4 * BH; i += NBLK * 128) VS0[i] = 0.f;
    gridbar(bar++);

    // Video recurrence: blocks 0..63 active (2 m-tiles x 32 j-tiles)
    const int vm0 = (blk & 1) * 32;
    const int vj0 = (blk >> 1) * 16;
    for (int t = 0; t < F; t++) {
        float* cur = (t & 1) ? VS1 : VS0;
        float* nxt = (t & 1) ? VS0 : VS1;
        if (blk < 64)
            step_tile<false>(cur, Whh_v1, nullptr, nullptr, GV, t, F,
                             cur, cur + BH, nxt, nxt + BH, VRAW, nullptr,
                             vm0, vj0, sH, sW);
        gridbar(bar++);
        if (blk < 64)
            step_tile<true>(VRAW, Wih_v2, cur + 2 * BH, Whh_v2, b_v2, t, F,
                            cur + 2 * BH, cur + 3 * BH, nxt + 2 * BH, nxt + 3 * BH,
                            nullptr, nullptr, vm0, vj0, sH, sW);
        gridbar(bar++);
    }

    // Broadcast final video states (in VS0) to per-(b,nc) text states
    for (int i = gtid; i < 4 * MH; i += NBLK * 128) {
        int a = i / MH;
        int r = i - a * MH;
        int m = r >> 9, jj = r & 511;
        TS0[i] = __ldcg(VS0 + (size_t)a * BH + (size_t)(m / NC) * H + jj);
    }
    gridbar(bar++);

    // Text recurrence: all 320 blocks (10 m-tiles x 32 j-tiles)
    const int tm0 = (blk % 10) * 32;
    const int tj0 = (blk / 10) * 16;
    for (int t = 0; t < L; t++) {
        float* cur = (t & 1) ? TS1 : TS0;
        float* nxt = (t & 1) ? TS0 : TS1;
        step_tile<false>(cur, Whh_t1, nullptr, nullptr, GT, t, L,
                         cur, cur + MH, nxt, nxt + MH, TRAW, qlen,
                         tm0, tj0, sH, sW);
        gridbar(bar++);
        step_tile<true>(TRAW, Wih_t2, cur + 2 * MH, Whh_t2, b_t2, t, L,
                        cur + 2 * MH, cur + 3 * MH, nxt + 2 * MH, nxt + 3 * MH,
                        nullptr, qlen, tm0, tj0, sH, sW);
        gridbar(bar++);
    }
}

// ---------------------------------------------------------------------------
// Tensor-core TN GEMM: C[M,N] = A[M,K] @ W[N,K]^T (+bias). 3xTF32.
// 256 threads, block tile 64x128, BK=16, distance-2 cp.async prefetch.
// Warps 2(m) x 4(n): warp tile 32x32. Requires M%64==0, N%128==0, K%16==0.
// ---------------------------------------------------------------------------
__global__ void __launch_bounds__(256) gemm_tc(
    const float* __restrict__ A, const float* __restrict__ W,
    const float* __restrict__ bias, float* __restrict__ Cmat,
    int M, int N, int K)
{
    __shared__ float sA[2][64][20];
    __shared__ float sB[2][128][20];
    const int tid = threadIdx.x;
    const int lane = tid & 31, warp = tid >> 5;
    const int wm = warp & 1, wn = warp >> 1;
    const int g8 = lane >> 2, t4 = lane & 3;
    const int bm = blockIdx.y * 64, bn = blockIdx.x * 128;

    float acc[2][4][4] = {};
    const int NCH = K / 16;

    auto issue = [&](int c, int buf) {
        {
            int r = tid >> 2, k4 = (tid & 3) << 2;
            cp_async16(&sA[buf][r][k4], A + (size_t)(bm + r) * K + c * 16 + k4);
        }
#pragma unroll
        for (int q = 0; q < 2; q++) {
            int v = tid + q * 256;
            int r = v >> 2, k4 = (v & 3) << 2;
            cp_async16(&sB[buf][r][k4], W + (size_t)(bn + r) * K + c * 16 + k4);
        }
    };

    issue(0, 0); CP_COMMIT;
    issue(1, 1); CP_COMMIT;
    for (int c = 0; c < NCH; c++) {
        if (c < NCH - 1) { CP_WAIT1; } else { CP_WAIT0; }
        __syncthreads();
        const int buf = c & 1;
#pragma unroll
        for (int kk = 0; kk < 2; kk++) {
            const int k0 = kk * 8;
            uint32_t ahi[2][4], alo[2][4];
#pragma unroll
            for (int mt = 0; mt < 2; mt++) {
                int r = wm * 32 + mt * 16 + g8;
                split_tf32(sA[buf][r][k0 + t4],         ahi[mt][0], alo[mt][0]);
                split_tf32(sA[buf][r + 8][k0 + t4],     ahi[mt][1], alo[mt][1]);
                split_tf32(sA[buf][r][k0 + t4 + 4],     ahi[mt][2], alo[mt][2]);
                split_tf32(sA[buf][r + 8][k0 + t4 + 4], ahi[mt][3], alo[mt][3]);
            }
#pragma unroll
            for (int nt = 0; nt < 4; nt++) {
                int n = wn * 32 + nt * 8 + g8;
                uint32_t bh0, bl0, bh1, bl1;
                split_tf32(sB[buf][n][k0 + t4],     bh0, bl0);
                split_tf32(sB[buf][n][k0 + t4 + 4], bh1, bl1);
#pragma unroll
                for (int mt = 0; mt < 2; mt++) {
                    mma8(acc[mt][nt], ahi[mt], bh0, bh1);
                    mma8(acc[mt][nt], ahi[mt], bl0, bl1);
                    mma8(acc[mt][nt], alo[mt], bh0, bh1);
                }
            }
        }
        __syncthreads();
        if (c + 2 < NCH) { issue(c + 2, buf); CP_COMMIT; }
    }

#pragma unroll
    for (int mt = 0; mt < 2; mt++) {
#pragma unroll
        for (int rr = 0; rr < 2; rr++) {
            int m = bm + wm * 32 + mt * 16 + g8 + rr * 8;
#pragma unroll
            for (int nt = 0; nt < 4; nt++) {
                int n = bn + wn * 32 + nt * 8 + t4 * 2;
                float v0 = acc[mt][nt][rr * 2 + 0];
                float v1 = acc[mt][nt][rr * 2 + 1];
                if (bias) { v0 += bias[n]; v1 += bias[n + 1]; }
                *(float2*)(Cmat + (size_t)m * N + n) = make_float2(v0, v1);
            }
        }
    }
}

// ---------------------------------------------------------------------------
// Small helper kernels
// ---------------------------------------------------------------------------
__global__ void zero_bars_k() {
    if (threadIdx.x < 128) g_bars[threadIdx.x] = 0u;
}

__global__ void pad_w_k(const float* __restrict__ src, float* __restrict__ dst) {
    int i = blockIdx.x * 256 + threadIdx.x;
    if (i >= cfg::G4 * cfg::EP) return;
    int n = i / cfg::EP, k = i - n * cfg::EP;
    dst[i] = (k < cfg::E) ? src[(size_t)n * cfg::E + k] : 0.f;
}

__global__ void embed_gather_k(const int* __restrict__ q, const float* __restrict__ emb,
                               float* __restrict__ dst) {
    int i = blockIdx.x * 256 + threadIdx.x;
    if (i >= cfg::MT * cfg::L * cfg::EP) return;
    int r = i / cfg::EP, k = i - r * cfg::EP;   // r = m*20 + t
    dst[i] = (k < cfg::E) ? emb[(size_t)q[r] * cfg::E + k] : 0.f;
}

__global__ void concat_k(const float* __restrict__ h1, const float* __restrict__ h2,
                         float* __restrict__ st) {
    int i = blockIdx.x * 256 + threadIdx.x;
    if (i >= cfg::MT * 2 * cfg::H) return;
    int m = i / (2 * cfg::H), jj = i - m * 2 * cfg::H;
    st[i] = (jj < cfg::H) ? h1[(size_t)m * cfg::H + jj]
                          : h2[(size_t)m * cfg::H + (jj - cfg::H)];
}

__global__ void rowdot_k(const float* __restrict__ fe, const float* __restrict__ w,
                         const float* __restrict__ b, float* __restrict__ out) {
    int warp = (blockIdx.x * blockDim.x + threadIdx.x) >> 5;
    int lane = threadIdx.x & 31;
    if (warp >= cfg::MT) return;
    const float* row = fe + (size_t)warp * (2 * cfg::H);
    float s = 0.f;
    for (int k = lane; k < 2 * cfg::H; k += 32) s += row[k] * w[k];
#pragma unroll
    for (int o = 16; o; o >>= 1) s += __shfl_xor_sync(0xffffffffu, s, o);
    if (lane == 0) out[warp] = s + b[0];
}

// d_out layout: outputs[320] then predictions[64] as float; tail zero.
__global__ void finalize_k(const float* __restrict__ outv, float* __restrict__ dout,
                           int out_size) {
    int i = blockIdx.x * 256 + threadIdx.x;
    if (i >= out_size) return;
    if (i < cfg::MT) {
        dout[i] = outv[i];
    } else if (i < cfg::MT + cfg::B) {
        int b = i - cfg::MT;
        float best = outv[b * cfg::NC]; int bi = 0;
#pragma unroll
        for (int nc = 1; nc < cfg::NC; nc++) {
            float v = outv[b * cfg::NC + nc];
            if (v > best) { best = v; bi = nc; }
        }
        dout[i] = (float)bi;
    } else {
        dout[i] = 0.f;
    }
}

// ---------------------------------------------------------------------------
// Host launcher (graph-capturable: kernel launches only)
// ---------------------------------------------------------------------------
extern "C" void kernel_launch(void* const* d_in, const int* in_sizes, int n_in,
                              void* d_out, int out_size) {
    using namespace cfg;
    const float* vf       = (const float*)d_in[0];
    const int*   questions= (const int*)  d_in[1];
    const int*   qlen     = (const int*)  d_in[2];
    const float* embw     = (const float*)d_in[3];
    const float* Wih_t1   = (const float*)d_in[4];
    const float* Whh_t1   = (const float*)d_in[5];
    const float* b_t1     = (const float*)d_in[6];
    const float* Wih_t2   = (const float*)d_in[7];
    const float* Whh_t2   = (const float*)d_in[8];
    const float* b_t2     = (const float*)d_in[9];
    const float* Wih_v1   = (const float*)d_in[10];
    const float* Whh_v1   = (const float*)d_in[11];
    const float* b_v1     = (const float*)d_in[12];
    const float* Wih_v2   = (const float*)d_in[13];
    const float* Whh_v2   = (const float*)d_in[14];
    const float* b_v2     = (const float*)d_in[15];
    const float* dec1_w   = (const float*)d_in[16];
    const float* dec1_b   = (const float*)d_in[17];
    const float* dec2_w   = (const float*)d_in[18];
    const float* dec2_b   = (const float*)d_in[19];
    (void)in_sizes; (void)n_in;

    float* S = nullptr;
    cudaGetSymbolAddress((void**)&S, g_scratch);
    float* GV   = S + OFF_GV;
    float* GT   = S + OFF_GT;
    float* XT   = S + OFF_XT;
    float* WT1P = S + OFF_WT1P;
    float* VS0  = S + OFF_VS0;
    float* VS1  = S + OFF_VS1;
    float* VRAW = S + OFF_VRAW;
    float* TS0  = S + OFF_TS0;
    float* TS1  = S + OFF_TS1;
    float* TRAW = S + OFF_TRAW;
    float* ST   = S + OFF_ST;
    float* FE   = S + OFF_FE;
    float* OUTV = S + OFF_OUT;
    float* dout = (float*)d_out;

    // Stage padded weight + gathered/padded embeddings; reset grid barriers
    zero_bars_k<<<1, 128>>>();
    pad_w_k<<<(G4 * EP + 255) / 256, 256>>>(Wih_t1, WT1P);
    embed_gather_k<<<(MT * L * EP + 255) / 256, 256>>>(questions, embw, XT);

    // Big time-parallel input-gate GEMMs on tensor cores
    gemm_tc<<<dim3(G4 / 128, (B * F) / 64), 256>>>(vf, Wih_v1, b_v1, GV, B * F, G4, C);
    gemm_tc<<<dim3(G4 / 128, (MT * L) / 64), 256>>>(XT, WT1P, b_t1, GT, MT * L, G4, EP);

    // Entire recurrence in one persistent kernel
    recurrence_k<<<NBLK, 128>>>(GV, GT,
                                Whh_v1, Wih_v2, Whh_v2, b_v2,
                                Whh_t1, Wih_t2, Whh_t2, b_t2,
                                qlen, VS0, VS1, VRAW, TS0, TS1, TRAW);

    // Decoder
    concat_k<<<(MT * 2 * H + 255) / 256, 256>>>(TS0, TS0 + 2 * MH, ST);
    gemm_tc<<<dim3((2 * H) / 128, MT / 64), 256>>>(ST, dec1_w, dec1_b, FE,
                                                   MT, 2 * H, 2 * H);
    rowdot_k<<<40, 256>>>(FE, dec2_w, dec2_b, OUTV);
    finalize_k<<<(out_size + 255) / 256, 256>>>(OUTV, dout, out_size);
}